// round 11
// baseline (speedup 1.0000x reference)
#include <cuda_runtime.h>
#include <cuda_fp16.h>

#define NU 100000
#define NE 100000
#define NN 200000
#define C  64
#define N_HOPS 3
#define NT (NE + NN + NU)            // combined destination space
#define MAXREC 4000000               // E + E2 + NNZ
#define SCAN_BLK 1024
#define NB ((NT + SCAN_BLK - 1) / SCAN_BLK)

// -------- persistent scratch (static device globals) --------
__device__ __align__(16) __half g_all0[(size_t)NN * C];  // ping (fp16)
__device__ __align__(16) __half g_all1[(size_t)NN * C];  // pong (fp16)
__device__ __align__(16) __half g_wh[32 * C];            // combined weight tables (fp16)
__device__ __align__(16) float  g_f[2 * NE];             // ||sum||/cnt, double-buffered
__device__ int   g_cnt[NT];
__device__ int   g_rowptr[NT + 1];
__device__ int   g_cursor[NT];
__device__ int   g_blocksums[NB];
__device__ int   g_dhist[192];                           // 3 regions x 64 degree bins
__device__ int   g_perm[NT];                             // degree-sorted row permutation
__device__ int   g_reci[MAXREC];                         // packed edge rec / im col
__device__ float g_recv[1000000];                        // im values (CSR tail)

// buffer written by gather hop h (h = -1 means the initial embedding buffer)
__device__ __forceinline__ const __half* buf_of(int h) {
    return (h & 1) ? g_all0 : g_all1;
}
__device__ __forceinline__ __half* buf_of_mut(int h) {
    return (h & 1) ? g_all0 : g_all1;
}

// ---------------------------------------------------------------------------
// init: g_all0 = fp16([user_emb ; entity_emb]); zero g_cnt + g_dhist; fp16 weights
// ---------------------------------------------------------------------------
__global__ void init_kernel(const float* __restrict__ user_emb,
                            const float* __restrict__ entity_emb,
                            const float* __restrict__ w,
                            const float* __restrict__ w2) {
    const size_t nn4   = (size_t)NN * C / 4;
    const size_t nu4   = (size_t)NU * C / 4;
    const size_t cnt4  = NT / 4;
    const size_t dh4   = 192 / 4;
    const size_t total = nn4 + cnt4 + dh4 + 31 * C;
    uint2*        all2 = (uint2*)g_all0;
    const float4* ue4  = (const float4*)user_emb;
    const float4* ee4  = (const float4*)entity_emb;
    for (size_t i = (size_t)blockIdx.x * blockDim.x + threadIdx.x;
         i < total; i += (size_t)gridDim.x * blockDim.x) {
        if (i < nn4) {
            float4 v = (i < nu4) ? ue4[i] : ee4[i - nu4];
            uint2 h;
            *(__half2*)&h.x = __floats2half2_rn(v.x, v.y);
            *(__half2*)&h.y = __floats2half2_rn(v.z, v.w);
            all2[i] = h;
        } else if (i < nn4 + cnt4) {
            ((int4*)g_cnt)[i - nn4] = make_int4(0, 0, 0, 0);
        } else if (i < nn4 + cnt4 + dh4) {
            ((int4*)g_dhist)[i - nn4 - cnt4] = make_int4(0, 0, 0, 0);
        } else {
            size_t j = i - nn4 - cnt4 - dh4;
            float x = (j < 15 * C) ? w[j] : w2[j - 15 * C];
            g_wh[j] = __float2half_rn(x);
        }
    }
}

// ---------------------------------------------------------------------------
// CSR build (one-time)
// dest space: [0,NE): entity edges | [NE,NE+NN): node edges | [NE+NN,NT): im
// ---------------------------------------------------------------------------
__global__ void hist_kernel(const int* __restrict__ ei,
                            const int* __restrict__ e2i,
                            const int* __restrict__ im_row,
                            int E, int E2, int NNZ) {
    int i = blockIdx.x * blockDim.x + threadIdx.x;
    int total = E + E2 + NNZ;
    if (i >= total) return;
    int d;
    if (i < E)           d = ei[i];
    else if (i < E + E2) d = NE + e2i[i - E];
    else                 d = NE + NN + im_row[i - E - E2];
    atomicAdd(g_cnt + d, 1);
}

__global__ void scan1_kernel() {
    __shared__ int s[256];
    int tid  = threadIdx.x;
    int base = blockIdx.x * SCAN_BLK + tid * 4;
    int v[4], t = 0;
    #pragma unroll
    for (int k = 0; k < 4; k++) {
        v[k] = (base + k < NT) ? g_cnt[base + k] : 0;
        t += v[k];
    }
    s[tid] = t;
    __syncthreads();
    #pragma unroll
    for (int off = 1; off < 256; off <<= 1) {
        int x = (tid >= off) ? s[tid - off] : 0;
        __syncthreads();
        s[tid] += x;
        __syncthreads();
    }
    int excl = s[tid] - t;
    if (tid == 255) g_blocksums[blockIdx.x] = s[255];
    int run = excl;
    #pragma unroll
    for (int k = 0; k < 4; k++) {
        if (base + k < NT) g_rowptr[base + k] = run;
        run += v[k];
    }
}

__global__ void scan2_kernel() {
    __shared__ int s[512];
    int tid = threadIdx.x;
    int v = (tid < NB) ? g_blocksums[tid] : 0;
    s[tid] = v;
    __syncthreads();
    #pragma unroll
    for (int off = 1; off < 512; off <<= 1) {
        int x = (tid >= off) ? s[tid - off] : 0;
        __syncthreads();
        s[tid] += x;
        __syncthreads();
    }
    if (tid < NB) g_blocksums[tid] = s[tid] - v;   // exclusive
}

__global__ void scan3_kernel(int total_rec) {
    int i = blockIdx.x * blockDim.x + threadIdx.x;
    if (i < NT) {
        int v = g_rowptr[i] + g_blocksums[i / SCAN_BLK];
        g_rowptr[i] = v;
        g_cursor[i] = v;
    }
    if (i == 0) g_rowptr[NT] = total_rec;
}

// edge recs pack (src_row*32 + weight_row) into one int; im recs = col + value
__global__ void fill_kernel(const int* __restrict__ ei,  const int* __restrict__ ety,
                            const int* __restrict__ e2i, const int* __restrict__ e2ty,
                            const int* __restrict__ im_row, const int* __restrict__ im_col,
                            const float* __restrict__ im_val,
                            int E, int E2, int NNZ) {
    int i = blockIdx.x * blockDim.x + threadIdx.x;
    int total = E + E2 + NNZ;
    if (i >= total) return;
    int EE2 = E + E2;
    int d, ival;
    float fval = 0.f;
    bool is_im = false;
    if (i < E) {
        d    = ei[i];
        ival = (NU + ei[E + i]) * 32 + (ety[i] - 1);
    } else if (i < EE2) {
        int e2 = i - E;
        d    = NE + e2i[e2];
        ival = e2i[E2 + e2] * 32 + (15 + e2ty[e2]);
    } else {
        int j = i - EE2;
        d     = NE + NN + im_row[j];
        ival  = im_col[j];
        fval  = im_val[j];
        is_im = true;
    }
    int pos = atomicAdd(g_cursor + d, 1);
    g_reci[pos] = ival;
    if (is_im) g_recv[pos - EE2] = fval;   // im recs occupy the CSR tail
}

// ---------------------------------------------------------------------------
// degree-sorted permutation build (region-preserving)
// ---------------------------------------------------------------------------
__global__ void deg_hist_kernel() {
    int i = blockIdx.x * blockDim.x + threadIdx.x;
    if (i >= NT) return;
    int r = (i < NE) ? 0 : (i < NE + NN) ? 1 : 2;
    int d = min(g_cnt[i], 63);
    atomicAdd(g_dhist + r * 64 + d, 1);
}

__global__ void deg_scan_kernel() {
    __shared__ int s[192];
    int t = threadIdx.x;
    if (t < 192) s[t] = g_dhist[t];
    __syncthreads();
    if (t < 3) {
        int base = (t == 0) ? 0 : (t == 1) ? NE : (NE + NN);
        int run = base;
        for (int d = 0; d < 64; d++) { int x = s[t * 64 + d]; s[t * 64 + d] = run; run += x; }
    }
    __syncthreads();
    if (t < 192) g_dhist[t] = s[t];
}

__global__ void deg_fill_kernel() {
    int i = blockIdx.x * blockDim.x + threadIdx.x;
    if (i >= NT) return;
    int r = (i < NE) ? 0 : (i < NE + NN) ? 1 : 2;
    int d = min(g_cnt[i], 63);
    int pos = atomicAdd(g_dhist + r * 64 + d, 1);
    g_perm[pos] = i;
}

// ---------------------------------------------------------------------------
// fused per-hop kernel: 8-lane group per destination row (degree-sorted slots)
// ---------------------------------------------------------------------------
__device__ __forceinline__ float grp_sum8(float s) {
    #pragma unroll
    for (int o = 4; o; o >>= 1) s += __shfl_xor_sync(0xffffffffu, s, o);
    return s;
}

struct F8 { float4 a, b; };

__device__ __forceinline__ F8 h8_to_f8(uint4 h) {
    F8 r;
    float2 p0 = __half22float2(*(__half2*)&h.x);
    float2 p1 = __half22float2(*(__half2*)&h.y);
    float2 p2 = __half22float2(*(__half2*)&h.z);
    float2 p3 = __half22float2(*(__half2*)&h.w);
    r.a = make_float4(p0.x, p0.y, p1.x, p1.y);
    r.b = make_float4(p2.x, p2.y, p3.x, p3.y);
    return r;
}

__global__ void __launch_bounds__(256) fused_kernel(
    int hop_g, int do_g, int hop_m, int do_m, int base, int EE2,
    const float* __restrict__ user_emb, const float* __restrict__ entity_emb,
    float* __restrict__ node_res, float* __restrict__ ent_out,
    float* __restrict__ user_res)
{
    int gslot = base + ((blockIdx.x * blockDim.x + threadIdx.x) >> 3);
    if (gslot >= NT) return;
    int gidx = __ldg(g_perm + gslot);      // region-preserving degree-sorted map
    int lane = threadIdx.x & 7;

    if (gidx < NE + NN) {
        // ---------------- gather path (hop_g) ----------------
        if (!do_g) return;
        const __half* prev = buf_of(hop_g - 1);
        __half*       next = buf_of_mut(hop_g);
        float*        fdst = g_f + (hop_g & 1) * NE;
        int hop0 = (hop_g == 0);

        int start = g_rowptr[gidx], end = g_rowptr[gidx + 1];
        float4 accA = make_float4(0.f, 0.f, 0.f, 0.f);
        float4 accB = make_float4(0.f, 0.f, 0.f, 0.f);
        int e = start;
        for (; e + 1 < end; e += 2) {
            int r0 = __ldg(g_reci + e);
            int r1 = __ldg(g_reci + e + 1);
            uint4 h0 = *((const uint4*)(prev + (size_t)(r0 >> 5) * C) + lane);
            uint4 h1 = *((const uint4*)(prev + (size_t)(r1 >> 5) * C) + lane);
            uint4 wh0 = *((const uint4*)(g_wh + (r0 & 31) * C) + lane);
            uint4 wh1 = *((const uint4*)(g_wh + (r1 & 31) * C) + lane);
            F8 s0 = h8_to_f8(h0), s1 = h8_to_f8(h1);
            F8 w0 = h8_to_f8(wh0), w1 = h8_to_f8(wh1);
            accA.x += s0.a.x * w0.a.x + s1.a.x * w1.a.x;
            accA.y += s0.a.y * w0.a.y + s1.a.y * w1.a.y;
            accA.z += s0.a.z * w0.a.z + s1.a.z * w1.a.z;
            accA.w += s0.a.w * w0.a.w + s1.a.w * w1.a.w;
            accB.x += s0.b.x * w0.b.x + s1.b.x * w1.b.x;
            accB.y += s0.b.y * w0.b.y + s1.b.y * w1.b.y;
            accB.z += s0.b.z * w0.b.z + s1.b.z * w1.b.z;
            accB.w += s0.b.w * w0.b.w + s1.b.w * w1.b.w;
        }
        if (e < end) {
            int r0 = __ldg(g_reci + e);
            uint4 h0 = *((const uint4*)(prev + (size_t)(r0 >> 5) * C) + lane);
            uint4 wh0 = *((const uint4*)(g_wh + (r0 & 31) * C) + lane);
            F8 s0 = h8_to_f8(h0);
            F8 w0 = h8_to_f8(wh0);
            accA.x += s0.a.x * w0.a.x; accA.y += s0.a.y * w0.a.y;
            accA.z += s0.a.z * w0.a.z; accA.w += s0.a.w * w0.a.w;
            accB.x += s0.b.x * w0.b.x; accB.y += s0.b.y * w0.b.y;
            accB.z += s0.b.z * w0.b.z; accB.w += s0.b.w * w0.b.w;
        }

        float ss = grp_sum8(accA.x * accA.x + accA.y * accA.y + accA.z * accA.z + accA.w * accA.w
                          + accB.x * accB.x + accB.y * accB.y + accB.z * accB.z + accB.w * accB.w);
        float n  = sqrtf(ss);
        float inv = 1.0f / fmaxf(n, 1e-12f);
        float4 oa = make_float4(accA.x * inv, accA.y * inv, accA.z * inv, accA.w * inv);
        float4 ob = make_float4(accB.x * inv, accB.y * inv, accB.z * inv, accB.w * inv);
        uint4 oh;
        *(__half2*)&oh.x = __floats2half2_rn(oa.x, oa.y);
        *(__half2*)&oh.y = __floats2half2_rn(oa.z, oa.w);
        *(__half2*)&oh.z = __floats2half2_rn(ob.x, ob.y);
        *(__half2*)&oh.w = __floats2half2_rn(ob.z, ob.w);

        if (gidx < NE) {
            *((uint4*)(next + (size_t)(NU + gidx) * C) + lane) = oh;
            if (lane == 0) fdst[gidx] = n / fmaxf((float)(end - start), 1.0f);
            if (hop_g == N_HOPS - 1) {
                float4* op = (float4*)(ent_out + (size_t)gidx * C) + lane * 2;
                op[0] = oa; op[1] = ob;
            }
        } else {
            int r = gidx - NE;
            if (r < NU) *((uint4*)(next + (size_t)r * C) + lane) = oh;
            float4* rp = (float4*)(node_res + (size_t)r * C) + lane * 2;
            float4 a0, a1;
            if (hop0) {
                const float4* ip = (r < NU)
                    ? (const float4*)(user_emb + (size_t)r * C) + lane * 2
                    : (const float4*)(entity_emb + (size_t)(r - NU) * C) + lane * 2;
                a0 = ip[0]; a1 = ip[1];
            } else {
                a0 = rp[0]; a1 = rp[1];
            }
            a0.x += oa.x; a0.y += oa.y; a0.z += oa.z; a0.w += oa.w;
            a1.x += ob.x; a1.y += ob.y; a1.z += ob.z; a1.w += ob.w;
            rp[0] = a0; rp[1] = a1;
        }
    } else {
        // ---------------- im path (hop_m) ----------------
        if (!do_m) return;
        const __half* src  = buf_of(hop_m);
        const float*  fsrc = g_f + (hop_m & 1) * NE;
        int hop0 = (hop_m == 0);
        int u = gidx - NE - NN;

        int start = g_rowptr[gidx], end = g_rowptr[gidx + 1];
        float4 accA = make_float4(0.f, 0.f, 0.f, 0.f);
        float4 accB = make_float4(0.f, 0.f, 0.f, 0.f);
        int e = start;
        for (; e + 1 < end; e += 2) {
            int c0i = __ldg(g_reci + e);
            int c1i = __ldg(g_reci + e + 1);
            float c0 = __ldg(g_recv + (e - EE2))     * __ldg(fsrc + c0i);
            float c1 = __ldg(g_recv + (e + 1 - EE2)) * __ldg(fsrc + c1i);
            uint4 h0 = *((const uint4*)(src + (size_t)(NU + c0i) * C) + lane);
            uint4 h1 = *((const uint4*)(src + (size_t)(NU + c1i) * C) + lane);
            F8 s0 = h8_to_f8(h0);
            F8 s1 = h8_to_f8(h1);
            accA.x += s0.a.x * c0 + s1.a.x * c1;
            accA.y += s0.a.y * c0 + s1.a.y * c1;
            accA.z += s0.a.z * c0 + s1.a.z * c1;
            accA.w += s0.a.w * c0 + s1.a.w * c1;
            accB.x += s0.b.x * c0 + s1.b.x * c1;
            accB.y += s0.b.y * c0 + s1.b.y * c1;
            accB.z += s0.b.z * c0 + s1.b.z * c1;
            accB.w += s0.b.w * c0 + s1.b.w * c1;
        }
        if (e < end) {
            int c0i = __ldg(g_reci + e);
            float c0 = __ldg(g_recv + (e - EE2)) * __ldg(fsrc + c0i);
            uint4 h0 = *((const uint4*)(src + (size_t)(NU + c0i) * C) + lane);
            F8 s0 = h8_to_f8(h0);
            accA.x += s0.a.x * c0; accA.y += s0.a.y * c0;
            accA.z += s0.a.z * c0; accA.w += s0.a.w * c0;
            accB.x += s0.b.x * c0; accB.y += s0.b.y * c0;
            accB.z += s0.b.z * c0; accB.w += s0.b.w * c0;
        }

        float ss = grp_sum8(accA.x * accA.x + accA.y * accA.y + accA.z * accA.z + accA.w * accA.w
                          + accB.x * accB.x + accB.y * accB.y + accB.z * accB.z + accB.w * accB.w);
        float inv = 1.0f / fmaxf(sqrtf(ss), 1e-12f);
        float4* rp = (float4*)(user_res + (size_t)u * C) + lane * 2;
        float4 a0, a1;
        if (hop0) {
            const float4* ip = (const float4*)(user_emb + (size_t)u * C) + lane * 2;
            a0 = ip[0]; a1 = ip[1];
        } else {
            a0 = rp[0]; a1 = rp[1];
        }
        a0.x += accA.x * inv; a0.y += accA.y * inv;
        a0.z += accA.z * inv; a0.w += accA.w * inv;
        a1.x += accB.x * inv; a1.y += accB.y * inv;
        a1.z += accB.z * inv; a1.w += accB.w * inv;
        rp[0] = a0; rp[1] = a1;
    }
}

// ---------------------------------------------------------------------------
extern "C" void kernel_launch(void* const* d_in, const int* in_sizes, int n_in,
                              void* d_out, int out_size) {
    const float* user_emb     = (const float*)d_in[0];
    const float* entity_emb   = (const float*)d_in[1];
    const float* weight       = (const float*)d_in[2];
    const float* extra_weight = (const float*)d_in[3];
    const float* im_val       = (const float*)d_in[4];
    const int*   edge_index   = (const int*)d_in[5];
    const int*   edge_type    = (const int*)d_in[6];
    const int*   extra_eidx   = (const int*)d_in[7];
    const int*   extra_etype  = (const int*)d_in[8];
    const int*   im_row       = (const int*)d_in[9];
    const int*   im_col       = (const int*)d_in[10];

    const int E   = in_sizes[6];
    const int E2  = in_sizes[8];
    const int NNZ = in_sizes[4];
    const int total_rec = E + E2 + NNZ;
    const int EE2 = E + E2;

    float* out      = (float*)d_out;
    float* user_res = out;                      // [NU, C]
    float* ent_out  = out + (size_t)NU * C;     // [NE, C]
    float* node_res = out + (size_t)NN * C;     // [NN, C]

    init_kernel<<<2048, 256>>>(user_emb, entity_emb, weight, extra_weight);
    hist_kernel<<<(total_rec + 255) / 256, 256>>>(edge_index, extra_eidx, im_row, E, E2, NNZ);
    scan1_kernel<<<NB, 256>>>();
    scan2_kernel<<<1, 512>>>();
    scan3_kernel<<<(NT + 255) / 256, 256>>>(total_rec);
    fill_kernel<<<(total_rec + 255) / 256, 256>>>(edge_index, edge_type,
                                                  extra_eidx, extra_etype,
                                                  im_row, im_col, im_val, E, E2, NNZ);
    deg_hist_kernel<<<(NT + 255) / 256, 256>>>();
    deg_scan_kernel<<<1, 192>>>();
    deg_fill_kernel<<<(NT + 255) / 256, 256>>>();

    const int g_blocks  = ((NE + NN) * 8 + 255) / 256;   // gather-only
    const int gm_blocks = (NT * 8 + 255) / 256;          // gather + im
    const int m_blocks  = (NU * 8 + 255) / 256;          // im-only

    // g0 ; [im0 || g1] ; [im1 || g2] ; im2
    fused_kernel<<<g_blocks, 256>>>(0, 1, 0, 0, 0, EE2,
                                    user_emb, entity_emb, node_res, ent_out, user_res);
    fused_kernel<<<gm_blocks, 256>>>(1, 1, 0, 1, 0, EE2,
                                     user_emb, entity_emb, node_res, ent_out, user_res);
    fused_kernel<<<gm_blocks, 256>>>(2, 1, 1, 1, 0, EE2,
                                     user_emb, entity_emb, node_res, ent_out, user_res);
    fused_kernel<<<m_blocks, 256>>>(0, 0, 2, 1, NE + NN, EE2,
                                    user_emb, entity_emb, node_res, ent_out, user_res);
}

// round 12
// speedup vs baseline: 1.1954x; 1.1954x over previous
#include <cuda_runtime.h>
#include <cuda_fp16.h>

#define NU 100000
#define NE 100000
#define NN 200000
#define C  64
#define N_HOPS 3
#define NT (NE + NN + NU)            // combined destination space
#define MAXREC 4000000               // E + E2 + NNZ
#define SCAN_BLK 1024
#define NB ((NT + SCAN_BLK - 1) / SCAN_BLK)

// -------- persistent scratch (static device globals) --------
__device__ __align__(16) __half g_all0[(size_t)NN * C];  // ping (fp16)
__device__ __align__(16) __half g_all1[(size_t)NN * C];  // pong (fp16)
__device__ __align__(16) __half g_wh[32 * C];            // combined weight tables (fp16)
__device__ __align__(16) float  g_f[2 * NE];             // ||sum||/cnt, double-buffered
__device__ int   g_cnt[NT];
__device__ int   g_rowptr[NT + 1];
__device__ int   g_cursor[NT];
__device__ int   g_blocksums[NB];
__device__ int   g_reci[MAXREC];                         // packed edge rec / im col
__device__ float g_recv[1000000];                        // im values (CSR tail)

// buffer written by gather hop h (h = -1 means the initial embedding buffer)
__device__ __forceinline__ const __half* buf_of(int h) {
    return (h & 1) ? g_all0 : g_all1;
}
__device__ __forceinline__ __half* buf_of_mut(int h) {
    return (h & 1) ? g_all0 : g_all1;
}

// ---------------------------------------------------------------------------
// zero g_cnt (must precede hist atomics)
// ---------------------------------------------------------------------------
__global__ void zero_cnt_kernel() {
    int i = blockIdx.x * blockDim.x + threadIdx.x;
    if (i < NT / 4) ((int4*)g_cnt)[i] = make_int4(0, 0, 0, 0);
}

// ---------------------------------------------------------------------------
// merged init + hist (independent tasks, one grid-stride kernel):
//  items [0, total_rec)                : hist atomics
//  items [total_rec, +nn4)             : fp16 conversion of embeddings
//  items [.., +31*C)                   : fp16 weight staging
// ---------------------------------------------------------------------------
__global__ void init_hist_kernel(const float* __restrict__ user_emb,
                                 const float* __restrict__ entity_emb,
                                 const float* __restrict__ w,
                                 const float* __restrict__ w2,
                                 const int* __restrict__ ei,
                                 const int* __restrict__ e2i,
                                 const int* __restrict__ im_row,
                                 int E, int E2, int NNZ) {
    const size_t rec_n = (size_t)E + E2 + NNZ;
    const size_t nn4   = (size_t)NN * C / 4;
    const size_t nu4   = (size_t)NU * C / 4;
    const size_t total = rec_n + nn4 + 31 * C;
    uint2*        all2 = (uint2*)g_all0;
    const float4* ue4  = (const float4*)user_emb;
    const float4* ee4  = (const float4*)entity_emb;
    for (size_t i = (size_t)blockIdx.x * blockDim.x + threadIdx.x;
         i < total; i += (size_t)gridDim.x * blockDim.x) {
        if (i < rec_n) {
            int d;
            if (i < (size_t)E)            d = ei[i];
            else if (i < (size_t)E + E2)  d = NE + e2i[i - E];
            else                          d = NE + NN + im_row[i - E - E2];
            atomicAdd(g_cnt + d, 1);
        } else if (i < rec_n + nn4) {
            size_t j = i - rec_n;
            float4 v = (j < nu4) ? ue4[j] : ee4[j - nu4];
            uint2 h;
            *(__half2*)&h.x = __floats2half2_rn(v.x, v.y);
            *(__half2*)&h.y = __floats2half2_rn(v.z, v.w);
            all2[j] = h;
        } else {
            size_t j = i - rec_n - nn4;
            float x = (j < 15 * C) ? w[j] : w2[j - 15 * C];
            g_wh[j] = __float2half_rn(x);
        }
    }
}

// ---------------------------------------------------------------------------
// CSR scan chain
// ---------------------------------------------------------------------------
__global__ void scan1_kernel() {
    __shared__ int s[256];
    int tid  = threadIdx.x;
    int base = blockIdx.x * SCAN_BLK + tid * 4;
    int v[4], t = 0;
    #pragma unroll
    for (int k = 0; k < 4; k++) {
        v[k] = (base + k < NT) ? g_cnt[base + k] : 0;
        t += v[k];
    }
    s[tid] = t;
    __syncthreads();
    #pragma unroll
    for (int off = 1; off < 256; off <<= 1) {
        int x = (tid >= off) ? s[tid - off] : 0;
        __syncthreads();
        s[tid] += x;
        __syncthreads();
    }
    int excl = s[tid] - t;
    if (tid == 255) g_blocksums[blockIdx.x] = s[255];
    int run = excl;
    #pragma unroll
    for (int k = 0; k < 4; k++) {
        if (base + k < NT) g_rowptr[base + k] = run;
        run += v[k];
    }
}

__global__ void scan2_kernel() {
    __shared__ int s[512];
    int tid = threadIdx.x;
    int v = (tid < NB) ? g_blocksums[tid] : 0;
    s[tid] = v;
    __syncthreads();
    #pragma unroll
    for (int off = 1; off < 512; off <<= 1) {
        int x = (tid >= off) ? s[tid - off] : 0;
        __syncthreads();
        s[tid] += x;
        __syncthreads();
    }
    if (tid < NB) g_blocksums[tid] = s[tid] - v;   // exclusive
}

__global__ void scan3_kernel(int total_rec) {
    int i = blockIdx.x * blockDim.x + threadIdx.x;
    if (i < NT) {
        int v = g_rowptr[i] + g_blocksums[i / SCAN_BLK];
        g_rowptr[i] = v;
        g_cursor[i] = v;
    }
    if (i == 0) g_rowptr[NT] = total_rec;
}

// edge recs pack (src_row*32 + weight_row) into one int; im recs = col + value
__global__ void fill_kernel(const int* __restrict__ ei,  const int* __restrict__ ety,
                            const int* __restrict__ e2i, const int* __restrict__ e2ty,
                            const int* __restrict__ im_row, const int* __restrict__ im_col,
                            const float* __restrict__ im_val,
                            int E, int E2, int NNZ) {
    int i = blockIdx.x * blockDim.x + threadIdx.x;
    int total = E + E2 + NNZ;
    if (i >= total) return;
    int EE2 = E + E2;
    int d, ival;
    float fval = 0.f;
    bool is_im = false;
    if (i < E) {
        d    = ei[i];
        ival = (NU + ei[E + i]) * 32 + (ety[i] - 1);
    } else if (i < EE2) {
        int e2 = i - E;
        d    = NE + e2i[e2];
        ival = e2i[E2 + e2] * 32 + (15 + e2ty[e2]);
    } else {
        int j = i - EE2;
        d     = NE + NN + im_row[j];
        ival  = im_col[j];
        fval  = im_val[j];
        is_im = true;
    }
    int pos = atomicAdd(g_cursor + d, 1);
    g_reci[pos] = ival;
    if (is_im) g_recv[pos - EE2] = fval;   // im recs occupy the CSR tail
}

// ---------------------------------------------------------------------------
// fused per-hop kernel: 8-lane group per destination row (natural row order)
// ---------------------------------------------------------------------------
__device__ __forceinline__ float grp_sum8(float s) {
    #pragma unroll
    for (int o = 4; o; o >>= 1) s += __shfl_xor_sync(0xffffffffu, s, o);
    return s;
}

struct F8 { float4 a, b; };

__device__ __forceinline__ F8 h8_to_f8(uint4 h) {
    F8 r;
    float2 p0 = __half22float2(*(__half2*)&h.x);
    float2 p1 = __half22float2(*(__half2*)&h.y);
    float2 p2 = __half22float2(*(__half2*)&h.z);
    float2 p3 = __half22float2(*(__half2*)&h.w);
    r.a = make_float4(p0.x, p0.y, p1.x, p1.y);
    r.b = make_float4(p2.x, p2.y, p3.x, p3.y);
    return r;
}

__global__ void __launch_bounds__(256) fused_kernel(
    int hop_g, int do_g, int hop_m, int do_m, int base, int EE2,
    const float* __restrict__ user_emb, const float* __restrict__ entity_emb,
    float* __restrict__ node_res, float* __restrict__ ent_out,
    float* __restrict__ user_res)
{
    int gidx = base + ((blockIdx.x * blockDim.x + threadIdx.x) >> 3);
    int lane = threadIdx.x & 7;

    if (gidx < NE + NN) {
        // ---------------- gather path (hop_g) ----------------
        if (!do_g) return;
        const __half* prev = buf_of(hop_g - 1);
        __half*       next = buf_of_mut(hop_g);
        float*        fdst = g_f + (hop_g & 1) * NE;
        int hop0 = (hop_g == 0);

        int start = g_rowptr[gidx], end = g_rowptr[gidx + 1];
        float4 accA = make_float4(0.f, 0.f, 0.f, 0.f);
        float4 accB = make_float4(0.f, 0.f, 0.f, 0.f);
        int e = start;
        for (; e + 1 < end; e += 2) {
            int r0 = __ldg(g_reci + e);
            int r1 = __ldg(g_reci + e + 1);
            uint4 h0 = *((const uint4*)(prev + (size_t)(r0 >> 5) * C) + lane);
            uint4 h1 = *((const uint4*)(prev + (size_t)(r1 >> 5) * C) + lane);
            uint4 wh0 = *((const uint4*)(g_wh + (r0 & 31) * C) + lane);
            uint4 wh1 = *((const uint4*)(g_wh + (r1 & 31) * C) + lane);
            F8 s0 = h8_to_f8(h0), s1 = h8_to_f8(h1);
            F8 w0 = h8_to_f8(wh0), w1 = h8_to_f8(wh1);
            accA.x += s0.a.x * w0.a.x + s1.a.x * w1.a.x;
            accA.y += s0.a.y * w0.a.y + s1.a.y * w1.a.y;
            accA.z += s0.a.z * w0.a.z + s1.a.z * w1.a.z;
            accA.w += s0.a.w * w0.a.w + s1.a.w * w1.a.w;
            accB.x += s0.b.x * w0.b.x + s1.b.x * w1.b.x;
            accB.y += s0.b.y * w0.b.y + s1.b.y * w1.b.y;
            accB.z += s0.b.z * w0.b.z + s1.b.z * w1.b.z;
            accB.w += s0.b.w * w0.b.w + s1.b.w * w1.b.w;
        }
        if (e < end) {
            int r0 = __ldg(g_reci + e);
            uint4 h0 = *((const uint4*)(prev + (size_t)(r0 >> 5) * C) + lane);
            uint4 wh0 = *((const uint4*)(g_wh + (r0 & 31) * C) + lane);
            F8 s0 = h8_to_f8(h0);
            F8 w0 = h8_to_f8(wh0);
            accA.x += s0.a.x * w0.a.x; accA.y += s0.a.y * w0.a.y;
            accA.z += s0.a.z * w0.a.z; accA.w += s0.a.w * w0.a.w;
            accB.x += s0.b.x * w0.b.x; accB.y += s0.b.y * w0.b.y;
            accB.z += s0.b.z * w0.b.z; accB.w += s0.b.w * w0.b.w;
        }

        float ss = grp_sum8(accA.x * accA.x + accA.y * accA.y + accA.z * accA.z + accA.w * accA.w
                          + accB.x * accB.x + accB.y * accB.y + accB.z * accB.z + accB.w * accB.w);
        float n  = sqrtf(ss);
        float inv = 1.0f / fmaxf(n, 1e-12f);
        float4 oa = make_float4(accA.x * inv, accA.y * inv, accA.z * inv, accA.w * inv);
        float4 ob = make_float4(accB.x * inv, accB.y * inv, accB.z * inv, accB.w * inv);
        uint4 oh;
        *(__half2*)&oh.x = __floats2half2_rn(oa.x, oa.y);
        *(__half2*)&oh.y = __floats2half2_rn(oa.z, oa.w);
        *(__half2*)&oh.z = __floats2half2_rn(ob.x, ob.y);
        *(__half2*)&oh.w = __floats2half2_rn(ob.z, ob.w);

        if (gidx < NE) {
            *((uint4*)(next + (size_t)(NU + gidx) * C) + lane) = oh;
            if (lane == 0) fdst[gidx] = n / fmaxf((float)(end - start), 1.0f);
            if (hop_g == N_HOPS - 1) {
                float4* op = (float4*)(ent_out + (size_t)gidx * C) + lane * 2;
                op[0] = oa; op[1] = ob;
            }
        } else {
            int r = gidx - NE;
            if (r < NU) *((uint4*)(next + (size_t)r * C) + lane) = oh;
            float4* rp = (float4*)(node_res + (size_t)r * C) + lane * 2;
            float4 a0, a1;
            if (hop0) {
                const float4* ip = (r < NU)
                    ? (const float4*)(user_emb + (size_t)r * C) + lane * 2
                    : (const float4*)(entity_emb + (size_t)(r - NU) * C) + lane * 2;
                a0 = ip[0]; a1 = ip[1];
            } else {
                a0 = rp[0]; a1 = rp[1];
            }
            a0.x += oa.x; a0.y += oa.y; a0.z += oa.z; a0.w += oa.w;
            a1.x += ob.x; a1.y += ob.y; a1.z += ob.z; a1.w += ob.w;
            rp[0] = a0; rp[1] = a1;
        }
    } else if (gidx < NT) {
        // ---------------- im path (hop_m) ----------------
        if (!do_m) return;
        const __half* src  = buf_of(hop_m);
        const float*  fsrc = g_f + (hop_m & 1) * NE;
        int hop0 = (hop_m == 0);
        int u = gidx - NE - NN;

        int start = g_rowptr[gidx], end = g_rowptr[gidx + 1];
        float4 accA = make_float4(0.f, 0.f, 0.f, 0.f);
        float4 accB = make_float4(0.f, 0.f, 0.f, 0.f);
        int e = start;
        for (; e + 1 < end; e += 2) {
            int c0i = __ldg(g_reci + e);
            int c1i = __ldg(g_reci + e + 1);
            float c0 = __ldg(g_recv + (e - EE2))     * __ldg(fsrc + c0i);
            float c1 = __ldg(g_recv + (e + 1 - EE2)) * __ldg(fsrc + c1i);
            uint4 h0 = *((const uint4*)(src + (size_t)(NU + c0i) * C) + lane);
            uint4 h1 = *((const uint4*)(src + (size_t)(NU + c1i) * C) + lane);
            F8 s0 = h8_to_f8(h0);
            F8 s1 = h8_to_f8(h1);
            accA.x += s0.a.x * c0 + s1.a.x * c1;
            accA.y += s0.a.y * c0 + s1.a.y * c1;
            accA.z += s0.a.z * c0 + s1.a.z * c1;
            accA.w += s0.a.w * c0 + s1.a.w * c1;
            accB.x += s0.b.x * c0 + s1.b.x * c1;
            accB.y += s0.b.y * c0 + s1.b.y * c1;
            accB.z += s0.b.z * c0 + s1.b.z * c1;
            accB.w += s0.b.w * c0 + s1.b.w * c1;
        }
        if (e < end) {
            int c0i = __ldg(g_reci + e);
            float c0 = __ldg(g_recv + (e - EE2)) * __ldg(fsrc + c0i);
            uint4 h0 = *((const uint4*)(src + (size_t)(NU + c0i) * C) + lane);
            F8 s0 = h8_to_f8(h0);
            accA.x += s0.a.x * c0; accA.y += s0.a.y * c0;
            accA.z += s0.a.z * c0; accA.w += s0.a.w * c0;
            accB.x += s0.b.x * c0; accB.y += s0.b.y * c0;
            accB.z += s0.b.z * c0; accB.w += s0.b.w * c0;
        }

        float ss = grp_sum8(accA.x * accA.x + accA.y * accA.y + accA.z * accA.z + accA.w * accA.w
                          + accB.x * accB.x + accB.y * accB.y + accB.z * accB.z + accB.w * accB.w);
        float inv = 1.0f / fmaxf(sqrtf(ss), 1e-12f);
        float4* rp = (float4*)(user_res + (size_t)u * C) + lane * 2;
        float4 a0, a1;
        if (hop0) {
            const float4* ip = (const float4*)(user_emb + (size_t)u * C) + lane * 2;
            a0 = ip[0]; a1 = ip[1];
        } else {
            a0 = rp[0]; a1 = rp[1];
        }
        a0.x += accA.x * inv; a0.y += accA.y * inv;
        a0.z += accA.z * inv; a0.w += accA.w * inv;
        a1.x += accB.x * inv; a1.y += accB.y * inv;
        a1.z += accB.z * inv; a1.w += accB.w * inv;
        rp[0] = a0; rp[1] = a1;
    }
}

// ---------------------------------------------------------------------------
extern "C" void kernel_launch(void* const* d_in, const int* in_sizes, int n_in,
                              void* d_out, int out_size) {
    const float* user_emb     = (const float*)d_in[0];
    const float* entity_emb   = (const float*)d_in[1];
    const float* weight       = (const float*)d_in[2];
    const float* extra_weight = (const float*)d_in[3];
    const float* im_val       = (const float*)d_in[4];
    const int*   edge_index   = (const int*)d_in[5];
    const int*   edge_type    = (const int*)d_in[6];
    const int*   extra_eidx   = (const int*)d_in[7];
    const int*   extra_etype  = (const int*)d_in[8];
    const int*   im_row       = (const int*)d_in[9];
    const int*   im_col       = (const int*)d_in[10];

    const int E   = in_sizes[6];
    const int E2  = in_sizes[8];
    const int NNZ = in_sizes[4];
    const int total_rec = E + E2 + NNZ;
    const int EE2 = E + E2;

    float* out      = (float*)d_out;
    float* user_res = out;                      // [NU, C]
    float* ent_out  = out + (size_t)NU * C;     // [NE, C]
    float* node_res = out + (size_t)NN * C;     // [NN, C]

    zero_cnt_kernel<<<(NT / 4 + 255) / 256, 256>>>();
    init_hist_kernel<<<2048, 256>>>(user_emb, entity_emb, weight, extra_weight,
                                    edge_index, extra_eidx, im_row, E, E2, NNZ);
    scan1_kernel<<<NB, 256>>>();
    scan2_kernel<<<1, 512>>>();
    scan3_kernel<<<(NT + 255) / 256, 256>>>(total_rec);
    fill_kernel<<<(total_rec + 255) / 256, 256>>>(edge_index, edge_type,
                                                  extra_eidx, extra_etype,
                                                  im_row, im_col, im_val, E, E2, NNZ);

    const int g_blocks  = ((NE + NN) * 8 + 255) / 256;   // gather-only
    const int gm_blocks = (NT * 8 + 255) / 256;          // gather + im
    const int m_blocks  = (NU * 8 + 255) / 256;          // im-only

    // g0 ; [im0 || g1] ; [im1 || g2] ; im2
    fused_kernel<<<g_blocks, 256>>>(0, 1, 0, 0, 0, EE2,
                                    user_emb, entity_emb, node_res, ent_out, user_res);
    fused_kernel<<<gm_blocks, 256>>>(1, 1, 0, 1, 0, EE2,
                                     user_emb, entity_emb, node_res, ent_out, user_res);
    fused_kernel<<<gm_blocks, 256>>>(2, 1, 1, 1, 0, EE2,
                                     user_emb, entity_emb, node_res, ent_out, user_res);
    fused_kernel<<<m_blocks, 256>>>(0, 0, 2, 1, NE + NN, EE2,
                                    user_emb, entity_emb, node_res, ent_out, user_res);
}